// round 2
// baseline (speedup 1.0000x reference)
#include <cuda_runtime.h>
#include <cstdint>

// Problem constants
#define E_    8
#define T_    2048
#define H_    2880
#define D_    2880
#define TWOD_ 5760

// Tiling
#define BM 128
#define BN 128
#define BK 32
#define ASTR 36    // BK + 4 pad -> conflict-free A frag reads
#define BSTR 136   // BN + 8 pad -> conflict-free B frag reads
#define AS_ELEMS (BM * ASTR)           // 4608
#define BS_ELEMS (BK * BSTR)           // 4352
#define SMEM_ELEMS (2 * (AS_ELEMS + BS_ELEMS))
#define SMEM_BYTES (SMEM_ELEMS * 4)    // 71680

// Scratch: hidden'[e][t][d] = rw[t,e] * glu_activation(...)  (188.7 MB)
__device__ float g_hidden[(size_t)E_ * T_ * D_];

__device__ __forceinline__ unsigned f2tf(float x) {
    unsigned r;
    asm("cvt.rna.tf32.f32 %0, %1;" : "=r"(r) : "f"(x));
    return r;
}

__device__ __forceinline__ void mma_tf32(float c[4], const unsigned a[4], const unsigned b[2]) {
    asm volatile(
        "mma.sync.aligned.m16n8k8.row.col.f32.tf32.tf32.f32 "
        "{%0,%1,%2,%3}, {%4,%5,%6,%7}, {%8,%9}, {%0,%1,%2,%3};\n"
        : "+f"(c[0]), "+f"(c[1]), "+f"(c[2]), "+f"(c[3])
        : "r"(a[0]), "r"(a[1]), "r"(a[2]), "r"(a[3]), "r"(b[0]), "r"(b[1]));
}

// Store staged registers (tf32-rounded) into one smem buffer pair.
__device__ __forceinline__ void stage_store(float* As, float* Bs,
                                            const float4* ar, const float4* br, int tid) {
#pragma unroll
    for (int it = 0; it < 4; it++) {
        int idx  = tid + it * 256;
        int rowa = idx >> 3, ca = (idx & 7) << 2;
        float* pa = As + rowa * ASTR + ca;
        pa[0] = __uint_as_float(f2tf(ar[it].x));
        pa[1] = __uint_as_float(f2tf(ar[it].y));
        pa[2] = __uint_as_float(f2tf(ar[it].z));
        pa[3] = __uint_as_float(f2tf(ar[it].w));
        int rowb = idx >> 5, cb = (idx & 31) << 2;
        float* pb = Bs + rowb * BSTR + cb;
        pb[0] = __uint_as_float(f2tf(br[it].x));
        pb[1] = __uint_as_float(f2tf(br[it].y));
        pb[2] = __uint_as_float(f2tf(br[it].z));
        pb[3] = __uint_as_float(f2tf(br[it].w));
    }
}

// One BK=32 slab of MMAs from a smem buffer pair.
__device__ __forceinline__ void compute_tile(const float* As, const float* Bs,
                                             float acc[2][8][4],
                                             int wm, int wn, int gid, int tig) {
#pragma unroll
    for (int kk = 0; kk < BK; kk += 8) {
        unsigned afr[2][4];
#pragma unroll
        for (int i = 0; i < 2; i++) {
            const float* p = As + (wm + i * 16 + gid) * ASTR + kk + tig;
            afr[i][0] = __float_as_uint(p[0]);
            afr[i][1] = __float_as_uint(p[8 * ASTR]);
            afr[i][2] = __float_as_uint(p[4]);
            afr[i][3] = __float_as_uint(p[8 * ASTR + 4]);
        }
        unsigned bfr[8][2];
#pragma unroll
        for (int j = 0; j < 8; j++) {
            const float* p = Bs + (kk + tig) * BSTR + wn + j * 8 + gid;
            bfr[j][0] = __float_as_uint(p[0]);
            bfr[j][1] = __float_as_uint(p[4 * BSTR]);
        }
#pragma unroll
        for (int i = 0; i < 2; i++)
#pragma unroll
            for (int j = 0; j < 8; j++)
                mma_tf32(acc[i][j], afr[i], bfr[j]);
    }
}

// ============================================================================
// GEMM1: gate_up = X @ W1[e] + b1[e]; fused GLU activation; scale by rw[t,e];
//        writes hidden' to g_hidden. All tile dims exact (no predication).
// ============================================================================
__global__ __launch_bounds__(256, 1)
void gemm1_kernel(const float* __restrict__ x, const float* __restrict__ w1,
                  const float* __restrict__ b1, const float* __restrict__ rw) {
    extern __shared__ float sm[];
    float* As0 = sm;
    float* As1 = sm + AS_ELEMS;
    float* Bs0 = sm + 2 * AS_ELEMS;
    float* Bs1 = sm + 2 * AS_ELEMS + BS_ELEMS;

    const int e  = blockIdx.z;
    const int n0 = blockIdx.x * BN;
    const int m0 = blockIdx.y * BM;
    const int tid  = threadIdx.x;
    const int lane = tid & 31;
    const int warp = tid >> 5;
    const int wm = (warp & 3) * 32;
    const int wn = (warp >> 2) * 64;
    const int gid = lane >> 2;
    const int tig = lane & 3;

    const float* Ag = x + (size_t)m0 * H_;
    const float* Bg = w1 + (size_t)e * H_ * TWOD_ + n0;

    float acc[2][8][4];
#pragma unroll
    for (int i = 0; i < 2; i++)
#pragma unroll
        for (int j = 0; j < 8; j++)
#pragma unroll
            for (int q = 0; q < 4; q++) acc[i][j][q] = 0.f;

    float4 ar[4], br[4];

    // prologue: stage tile 0
#pragma unroll
    for (int it = 0; it < 4; it++) {
        int idx  = tid + it * 256;
        int rowa = idx >> 3, ca = (idx & 7) << 2;
        ar[it] = *reinterpret_cast<const float4*>(Ag + (size_t)rowa * H_ + ca);
        int rowb = idx >> 5, cb = (idx & 31) << 2;
        br[it] = *reinterpret_cast<const float4*>(Bg + (size_t)rowb * TWOD_ + cb);
    }
    stage_store(As0, Bs0, ar, br, tid);
    __syncthreads();

    const int NKT = H_ / BK;  // 90
    int buf = 0;
    for (int kt = 0; kt < NKT; kt++) {
        if (kt + 1 < NKT) {
            const float* Ak = Ag + (kt + 1) * BK;
            const float* Bk = Bg + (size_t)(kt + 1) * BK * TWOD_;
#pragma unroll
            for (int it = 0; it < 4; it++) {
                int idx  = tid + it * 256;
                int rowa = idx >> 3, ca = (idx & 7) << 2;
                ar[it] = *reinterpret_cast<const float4*>(Ak + (size_t)rowa * H_ + ca);
                int rowb = idx >> 5, cb = (idx & 31) << 2;
                br[it] = *reinterpret_cast<const float4*>(Bk + (size_t)rowb * TWOD_ + cb);
            }
        }
        compute_tile(buf ? As1 : As0, buf ? Bs1 : Bs0, acc, wm, wn, gid, tig);
        if (kt + 1 < NKT) {
            stage_store(buf ? As0 : As1, buf ? Bs0 : Bs1, ar, br, tid);
            __syncthreads();
            buf ^= 1;
        }
    }

    // epilogue: bias + clamp + glu + routing-weight prescale -> g_hidden
    float rwv[2][2];
#pragma unroll
    for (int i = 0; i < 2; i++)
#pragma unroll
        for (int s = 0; s < 2; s++)
            rwv[i][s] = rw[(size_t)(m0 + wm + i * 16 + s * 8 + gid) * E_ + e];

    float* Hd = g_hidden + (size_t)e * T_ * D_;
#pragma unroll
    for (int i = 0; i < 2; i++) {
#pragma unroll
        for (int j = 0; j < 8; j++) {
            int col = n0 + wn + j * 8 + 2 * tig;  // even: gate at col, up at col+1
            float bg = b1[(size_t)e * TWOD_ + col];
            float bu = b1[(size_t)e * TWOD_ + col + 1];
#pragma unroll
            for (int s = 0; s < 2; s++) {
                float g = acc[i][j][2 * s]     + bg;
                float u = acc[i][j][2 * s + 1] + bu;
                g = fminf(g, 7.0f);
                u = fminf(fmaxf(u, -7.0f), 7.0f);
                float sig = 1.0f / (1.0f + __expf(-1.702f * g));
                float hv  = (u + 1.0f) * (g * sig);
                int row = m0 + wm + i * 16 + s * 8 + gid;
                Hd[(size_t)row * D_ + (col >> 1)] = rwv[i][s] * hv;
            }
        }
    }
}

// ============================================================================
// GEMM2: out[t,h] = sum_e hidden'[e,t,:] @ W2[e][:,h] + sum_e rw[t,e]*b2[e,h]
//        K stacked over experts (E*D = 23040). N tail predicated.
// ============================================================================
__global__ __launch_bounds__(256, 1)
void gemm2_kernel(const float* __restrict__ w2, const float* __restrict__ b2,
                  const float* __restrict__ rw, float* __restrict__ out) {
    extern __shared__ float sm[];
    float* As0 = sm;
    float* As1 = sm + AS_ELEMS;
    float* Bs0 = sm + 2 * AS_ELEMS;
    float* Bs1 = sm + 2 * AS_ELEMS + BS_ELEMS;

    const int n0 = blockIdx.x * BN;
    const int m0 = blockIdx.y * BM;
    const int tid  = threadIdx.x;
    const int lane = tid & 31;
    const int warp = tid >> 5;
    const int wm = (warp & 3) * 32;
    const int wn = (warp >> 2) * 64;
    const int gid = lane >> 2;
    const int tig = lane & 3;

    float acc[2][8][4];
#pragma unroll
    for (int i = 0; i < 2; i++)
#pragma unroll
        for (int j = 0; j < 8; j++)
#pragma unroll
            for (int q = 0; q < 4; q++) acc[i][j][q] = 0.f;

    float4 ar[4], br[4];

    const int KPE = D_ / BK;        // 90 k-tiles per expert
    const int NKT = E_ * KPE;       // 720

    // load for tile kt
    auto g2_load = [&](int kt) {
        int e   = kt / KPE;
        int kin = kt - e * KPE;
        const float* Ak = g_hidden + (size_t)e * T_ * D_ + (size_t)m0 * D_ + kin * BK;
        const float* Bk = w2 + (size_t)e * D_ * H_ + (size_t)(kin * BK) * H_;
#pragma unroll
        for (int it = 0; it < 4; it++) {
            int idx  = tid + it * 256;
            int rowa = idx >> 3, ca = (idx & 7) << 2;
            ar[it] = *reinterpret_cast<const float4*>(Ak + (size_t)rowa * D_ + ca);
            int rowb = idx >> 5, cb = (idx & 31) << 2;
            int col = n0 + cb;
            br[it] = (col < H_)
                         ? *reinterpret_cast<const float4*>(Bk + (size_t)rowb * H_ + col)
                         : make_float4(0.f, 0.f, 0.f, 0.f);
        }
    };

    g2_load(0);
    stage_store(As0, Bs0, ar, br, tid);
    __syncthreads();

    int buf = 0;
    for (int kt = 0; kt < NKT; kt++) {
        if (kt + 1 < NKT) g2_load(kt + 1);
        compute_tile(buf ? As1 : As0, buf ? Bs1 : Bs0, acc, wm, wn, gid, tig);
        if (kt + 1 < NKT) {
            stage_store(buf ? As0 : As1, buf ? Bs0 : Bs1, ar, br, tid);
            __syncthreads();
            buf ^= 1;
        }
    }

    // epilogue: add sum_e rw[t,e]*b2[e,h], write out (predicated on col<H)
    float rwr[2][2][E_];
#pragma unroll
    for (int i = 0; i < 2; i++)
#pragma unroll
        for (int s = 0; s < 2; s++) {
            int row = m0 + wm + i * 16 + s * 8 + gid;
#pragma unroll
            for (int ee = 0; ee < E_; ee++)
                rwr[i][s][ee] = rw[(size_t)row * E_ + ee];
        }

#pragma unroll
    for (int i = 0; i < 2; i++) {
#pragma unroll
        for (int j = 0; j < 8; j++) {
            int col = n0 + wn + j * 8 + 2 * tig;
            if (col < H_) {
#pragma unroll
                for (int s = 0; s < 2; s++) {
                    int row = m0 + wm + i * 16 + s * 8 + gid;
                    float bs0 = 0.f, bs1 = 0.f;
#pragma unroll
                    for (int ee = 0; ee < E_; ee++) {
                        float r = rwr[i][s][ee];
                        bs0 += r * b2[(size_t)ee * H_ + col];
                        bs1 += r * b2[(size_t)ee * H_ + col + 1];
                    }
                    out[(size_t)row * H_ + col]     = acc[i][j][2 * s]     + bs0;
                    out[(size_t)row * H_ + col + 1] = acc[i][j][2 * s + 1] + bs1;
                }
            }
        }
    }
}

extern "C" void kernel_launch(void* const* d_in, const int* in_sizes, int n_in,
                              void* d_out, int out_size) {
    (void)in_sizes; (void)n_in; (void)out_size;
    const float* x  = (const float*)d_in[0];  // hidden_states [2,1024,2880]
    const float* rw = (const float*)d_in[1];  // routing_weights [2048,8]
    const float* w1 = (const float*)d_in[2];  // gate_up_proj [8,2880,5760]
    const float* b1 = (const float*)d_in[3];  // gate_up_proj_bias [8,5760]
    const float* w2 = (const float*)d_in[4];  // down_proj [8,2880,2880]
    const float* b2 = (const float*)d_in[5];  // down_proj_bias [8,2880]
    float* out = (float*)d_out;               // [2,1024,2880] f32

    cudaFuncSetAttribute(gemm1_kernel, cudaFuncAttributeMaxDynamicSharedMemorySize, SMEM_BYTES);
    cudaFuncSetAttribute(gemm2_kernel, cudaFuncAttributeMaxDynamicSharedMemorySize, SMEM_BYTES);

    gemm1_kernel<<<dim3(TWOD_ / BN, T_ / BM, E_), 256, SMEM_BYTES>>>(x, w1, b1, rw);
    gemm2_kernel<<<dim3((H_ + BN - 1) / BN, T_ / BM, 1), 256, SMEM_BYTES>>>(w2, b2, rw, out);
}

// round 4
// speedup vs baseline: 2.4971x; 2.4971x over previous
#include <cuda_runtime.h>
#include <cuda_fp16.h>
#include <cstdint>

#define E_    8
#define T_    2048
#define H_    2880
#define D_    2880
#define TWOD_ 5760

#define BM 128
#define BN 128
#define BK 64                       // fp16 k per slab (128B rows, SW128 swizzle)
#define NS 3                        // cp.async stages
#define A_BYTES (BM * BK * 2)       // 16384
#define B_BYTES (BN * BK * 2)       // 16384
#define STAGE_BYTES (A_BYTES + B_BYTES)
#define SMEM_BYTES (NS * STAGE_BYTES)   // 98304

// ---------------- fp16 scratch ----------------
__device__ __align__(1024) __half g_w1t[(size_t)E_ * TWOD_ * H_];  // [e][n][k]
__device__ __align__(1024) __half g_w2t[(size_t)E_ * H_ * D_];     // [e][h][d]
__device__ __align__(1024) __half g_xh[(size_t)T_ * H_];           // [t][k]
__device__ __align__(1024) __half g_hid[(size_t)E_ * T_ * D_];     // [e][t][d]

// ---------------- PTX helpers (base ISA only: sm_80-era) ----------------
__device__ __forceinline__ uint32_t smem_u32(const void* p) {
    uint32_t a;
    asm("{ .reg .u64 t; cvta.to.shared.u64 t, %1; cvt.u32.u64 %0, t; }" : "=r"(a) : "l"(p));
    return a;
}
__device__ __forceinline__ void cpa16(uint32_t dst, const void* src, int sz) {
    asm volatile("cp.async.cg.shared.global [%0], [%1], 16, %2;"
                 :: "r"(dst), "l"(src), "r"(sz) : "memory");
}
#define CP_COMMIT() asm volatile("cp.async.commit_group;" ::: "memory")
#define CP_WAIT(n)  asm volatile("cp.async.wait_group %0;" :: "n"(n) : "memory")

__device__ __forceinline__ void ldsm4(uint32_t (&r)[4], uint32_t addr) {
    asm volatile("ldmatrix.sync.aligned.m8n8.x4.shared.b16 {%0,%1,%2,%3}, [%4];"
                 : "=r"(r[0]), "=r"(r[1]), "=r"(r[2]), "=r"(r[3]) : "r"(addr));
}
__device__ __forceinline__ void mma16816(float c[4], const uint32_t a[4], const uint32_t b[2]) {
    asm volatile("mma.sync.aligned.m16n8k16.row.col.f32.f16.f16.f32 "
                 "{%0,%1,%2,%3}, {%4,%5,%6,%7}, {%8,%9}, {%0,%1,%2,%3};"
                 : "+f"(c[0]), "+f"(c[1]), "+f"(c[2]), "+f"(c[3])
                 : "r"(a[0]), "r"(a[1]), "r"(a[2]), "r"(a[3]), "r"(b[0]), "r"(b[1]));
}

// swizzled address within a [rows][64 halves] tile, 128B rows, Swizzle<3,4,3>
__device__ __forceinline__ uint32_t swaddr(uint32_t base, int row, int colbyte) {
    return base + row * 128 + (colbyte ^ ((row & 7) << 4));
}

// ---------------- prep kernels ----------------
__global__ void k_cvt_half(const float* __restrict__ src) {
    const float2* s2 = (const float2*)src;
    __half2* d2 = (__half2*)g_xh;
    size_t n = (size_t)T_ * H_ / 2;
    for (size_t i = (size_t)blockIdx.x * blockDim.x + threadIdx.x; i < n;
         i += (size_t)gridDim.x * blockDim.x) {
        float2 v = s2[i];
        d2[i] = __floats2half2_rn(v.x, v.y);
    }
}
// dst[z][c][r] = (half)src[z][r][c]; src [Z][R][C]; tiles 64(r) x 32(c)
__global__ void k_transpose_h(const float* __restrict__ src, __half* __restrict__ dst, int R, int C) {
    __shared__ float t[32][65];
    size_t zs = (size_t)blockIdx.z * R * C;
    int r0 = blockIdx.y * 64, c0 = blockIdx.x * 32;
    int tx = threadIdx.x, ty = threadIdx.y;
#pragma unroll
    for (int i = 0; i < 8; i++) {
        int r = ty + i * 8;
        t[tx][r] = src[zs + (size_t)(r0 + r) * C + c0 + tx];
    }
    __syncthreads();
    __half2* d2 = (__half2*)(dst + zs);
#pragma unroll
    for (int j = 0; j < 4; j++) {
        int c = ty + j * 8;
        d2[((size_t)(c0 + c) * R + r0) / 2 + tx] = __floats2half2_rn(t[c][2 * tx], t[c][2 * tx + 1]);
    }
}

// ============================================================================
// Shared mainloop pieces (macro-free inline functions, per-kernel lambdas do IO)
// ============================================================================
struct Frag {
    float acc[2][8][4];
};

__device__ __forceinline__ void compute_slab(uint32_t sA, uint32_t sB, Frag& F,
                                             int wm, int wn, int lane) {
    const int l7 = lane & 7, l15 = lane & 15;
    const int lb8 = (lane >> 3) & 1, lb16 = (lane >> 4) & 1;
#pragma unroll
    for (int kk = 0; kk < BK / 16; kk++) {
        uint32_t a[2][4];
#pragma unroll
        for (int i = 0; i < 2; i++) {
            int row = wm + i * 16 + l15;
            ldsm4(a[i], swaddr(sA, row, (kk << 5) | (lb16 << 4)));
        }
        uint32_t b[8][2];
#pragma unroll
        for (int jj = 0; jj < 4; jj++) {
            int row = wn + jj * 16 + l7 + (lb16 << 3);
            uint32_t t[4];
            ldsm4(t, swaddr(sB, row, (kk << 5) | (lb8 << 4)));
            b[2 * jj][0] = t[0]; b[2 * jj][1] = t[1];
            b[2 * jj + 1][0] = t[2]; b[2 * jj + 1][1] = t[3];
        }
#pragma unroll
        for (int i = 0; i < 2; i++)
#pragma unroll
            for (int j = 0; j < 8; j++)
                mma16816(F.acc[i][j], a[i], b[j]);
    }
}

// ============================================================================
// GEMM1: hid[e,t,d] = rw[t,e] * glu(X @ W1[e] + b1[e])
// ============================================================================
__global__ __launch_bounds__(256, 1)
void gemm1_hk(const float* __restrict__ b1, const float* __restrict__ rw) {
    extern __shared__ __align__(1024) char smem[];
    const uint32_t sb = smem_u32(smem);
    const int tid = threadIdx.x, lane = tid & 31, warp = tid >> 5;
    const int wm = (warp & 3) * 32, wn = (warp >> 2) * 64;
    const int m0 = blockIdx.x * BM, n0 = blockIdx.y * BN, e = blockIdx.z;

    Frag F;
#pragma unroll
    for (int i = 0; i < 2; i++)
#pragma unroll
        for (int j = 0; j < 8; j++)
#pragma unroll
            for (int q = 0; q < 4; q++) F.acc[i][j][q] = 0.f;

    const __half* Ab = g_xh + (size_t)m0 * H_;
    const __half* Bb = g_w1t + ((size_t)e * TWOD_ + n0) * H_;

    auto copy_slab = [&](int kt, int buf) {
        uint32_t sA = sb + buf * STAGE_BYTES, sB = sA + A_BYTES;
        const __half* ga = Ab + kt * BK;
        const __half* gb = Bb + kt * BK;
#pragma unroll
        for (int it = 0; it < 4; it++) {
            int ch = tid + it * 256;
            int r = ch >> 3, kc = ch & 7;
            cpa16(swaddr(sA, r, kc * 16), ga + (size_t)r * H_ + kc * 8, 16);
        }
#pragma unroll
        for (int it = 0; it < 4; it++) {
            int ch = tid + it * 256;
            int r = ch >> 3, kc = ch & 7;
            cpa16(swaddr(sB, r, kc * 16), gb + (size_t)r * H_ + kc * 8, 16);
        }
    };

    const int NKT = H_ / BK;  // 45
    copy_slab(0, 0); CP_COMMIT();
    copy_slab(1, 1); CP_COMMIT();
    int buf = 0;
    for (int kt = 0; kt < NKT; kt++) {
        CP_WAIT(1);
        __syncthreads();
        if (kt + 2 < NKT) copy_slab(kt + 2, (buf + 2) % NS);
        CP_COMMIT();
        compute_slab(sb + buf * STAGE_BYTES, sb + buf * STAGE_BYTES + A_BYTES, F, wm, wn, lane);
        buf = (buf == NS - 1) ? 0 : buf + 1;
    }
    CP_WAIT(0);
    __syncthreads();

    // bias tile -> smem
    float* bsm = (float*)smem;
    for (int i = tid; i < BN; i += 256) bsm[i] = b1[(size_t)e * TWOD_ + n0 + i];
    __syncthreads();

    const int tig = lane & 3, gid = lane >> 2;
#pragma unroll
    for (int i = 0; i < 2; i++) {
#pragma unroll
        for (int s = 0; s < 2; s++) {
            int row = m0 + wm + i * 16 + s * 8 + gid;
            float rwv = rw[(size_t)row * E_ + e];
            __half* hd = g_hid + ((size_t)e * T_ + row) * D_ + (n0 >> 1);
#pragma unroll
            for (int j = 0; j < 8; j++) {
                int cl = wn + j * 8 + 2 * tig;
                float g = F.acc[i][j][2 * s]     + bsm[cl];
                float u = F.acc[i][j][2 * s + 1] + bsm[cl + 1];
                g = fminf(g, 7.0f);
                u = fminf(fmaxf(u, -7.0f), 7.0f);
                float sig = 1.0f / (1.0f + __expf(-1.702f * g));
                hd[cl >> 1] = __float2half_rn(rwv * (u + 1.0f) * (g * sig));
            }
        }
    }
}

// ============================================================================
// GEMM2: out[t,h] = sum_e hid[e,t,:] @ W2t[e][h,:] + sum_e rw[t,e]*b2[e,h]
// ============================================================================
__global__ __launch_bounds__(256, 1)
void gemm2_hk(const float* __restrict__ b2, const float* __restrict__ rw, float* __restrict__ out) {
    extern __shared__ __align__(1024) char smem[];
    const uint32_t sb = smem_u32(smem);
    const int tid = threadIdx.x, lane = tid & 31, warp = tid >> 5;
    const int wm = (warp & 3) * 32, wn = (warp >> 2) * 64;
    const int m0 = blockIdx.x * BM, n0 = blockIdx.y * BN;

    Frag F;
#pragma unroll
    for (int i = 0; i < 2; i++)
#pragma unroll
        for (int j = 0; j < 8; j++)
#pragma unroll
            for (int q = 0; q < 4; q++) F.acc[i][j][q] = 0.f;

    const int KPE = D_ / BK;      // 45
    const int NKT = E_ * KPE;     // 360

    auto copy_slab = [&](int kt, int buf) {
        int e = kt / KPE, kin = kt - e * KPE;
        uint32_t sA = sb + buf * STAGE_BYTES, sB = sA + A_BYTES;
        const __half* ga = g_hid + ((size_t)e * T_ + m0) * D_ + kin * BK;
        const __half* gb = g_w2t + ((size_t)e * H_ + n0) * D_ + kin * BK;
#pragma unroll
        for (int it = 0; it < 4; it++) {
            int ch = tid + it * 256;
            int r = ch >> 3, kc = ch & 7;
            cpa16(swaddr(sA, r, kc * 16), ga + (size_t)r * D_ + kc * 8, 16);
        }
#pragma unroll
        for (int it = 0; it < 4; it++) {
            int ch = tid + it * 256;
            int r = ch >> 3, kc = ch & 7;
            int ok = (n0 + r < H_) ? 16 : 0;     // tail rows zero-filled
            cpa16(swaddr(sB, r, kc * 16), gb + (size_t)r * D_ + kc * 8, ok);
        }
    };

    copy_slab(0, 0); CP_COMMIT();
    copy_slab(1, 1); CP_COMMIT();
    int buf = 0;
    for (int kt = 0; kt < NKT; kt++) {
        CP_WAIT(1);
        __syncthreads();
        if (kt + 2 < NKT) copy_slab(kt + 2, (buf + 2) % NS);
        CP_COMMIT();
        compute_slab(sb + buf * STAGE_BYTES, sb + buf * STAGE_BYTES + A_BYTES, F, wm, wn, lane);
        buf = (buf == NS - 1) ? 0 : buf + 1;
    }
    CP_WAIT(0);
    __syncthreads();

    // b2 tile -> smem: [8][128]
    float* b2s = (float*)smem;
    for (int i = tid; i < E_ * BN; i += 256) {
        int ee = i >> 7, c = i & 127;
        int gc = n0 + c;
        b2s[i] = (gc < H_) ? b2[(size_t)ee * H_ + gc] : 0.f;
    }
    __syncthreads();

    const int tig = lane & 3, gid = lane >> 2;
    float rwr[2][2][E_];
#pragma unroll
    for (int i = 0; i < 2; i++)
#pragma unroll
        for (int s = 0; s < 2; s++) {
            int row = m0 + wm + i * 16 + s * 8 + gid;
            const float4* rp = (const float4*)(rw + (size_t)row * E_);
            float4 r0 = rp[0], r1 = rp[1];
            rwr[i][s][0] = r0.x; rwr[i][s][1] = r0.y; rwr[i][s][2] = r0.z; rwr[i][s][3] = r0.w;
            rwr[i][s][4] = r1.x; rwr[i][s][5] = r1.y; rwr[i][s][6] = r1.z; rwr[i][s][7] = r1.w;
        }

#pragma unroll
    for (int j = 0; j < 8; j++) {
        int cl = wn + j * 8 + 2 * tig;
        int gc = n0 + cl;
        if (gc < H_) {
            float bb0[E_], bb1[E_];
#pragma unroll
            for (int ee = 0; ee < E_; ee++) {
                bb0[ee] = b2s[ee * BN + cl];
                bb1[ee] = b2s[ee * BN + cl + 1];
            }
#pragma unroll
            for (int i = 0; i < 2; i++)
#pragma unroll
                for (int s = 0; s < 2; s++) {
                    int row = m0 + wm + i * 16 + s * 8 + gid;
                    float bs0 = 0.f, bs1 = 0.f;
#pragma unroll
                    for (int ee = 0; ee < E_; ee++) {
                        bs0 += rwr[i][s][ee] * bb0[ee];
                        bs1 += rwr[i][s][ee] * bb1[ee];
                    }
                    float2 v = make_float2(F.acc[i][j][2 * s] + bs0,
                                           F.acc[i][j][2 * s + 1] + bs1);
                    *(float2*)(out + (size_t)row * H_ + gc) = v;
                }
        }
    }
}

// ---------------- host ----------------
extern "C" void kernel_launch(void* const* d_in, const int* in_sizes, int n_in,
                              void* d_out, int out_size) {
    (void)in_sizes; (void)n_in; (void)out_size;
    const float* x  = (const float*)d_in[0];
    const float* rw = (const float*)d_in[1];
    const float* w1 = (const float*)d_in[2];
    const float* b1 = (const float*)d_in[3];
    const float* w2 = (const float*)d_in[4];
    const float* b2 = (const float*)d_in[5];
    float* out = (float*)d_out;

    void *p_w1t, *p_w2t;
    cudaGetSymbolAddress(&p_w1t, g_w1t);
    cudaGetSymbolAddress(&p_w2t, g_w2t);

    cudaFuncSetAttribute(gemm1_hk, cudaFuncAttributeMaxDynamicSharedMemorySize, SMEM_BYTES);
    cudaFuncSetAttribute(gemm2_hk, cudaFuncAttributeMaxDynamicSharedMemorySize, SMEM_BYTES);

    k_cvt_half<<<2048, 256>>>(x);
    k_transpose_h<<<dim3(TWOD_ / 32, H_ / 64, E_), dim3(32, 8)>>>(w1, (__half*)p_w1t, H_, TWOD_);
    k_transpose_h<<<dim3(H_ / 32, D_ / 64, E_), dim3(32, 8)>>>(w2, (__half*)p_w2t, D_, H_);

    gemm1_hk<<<dim3(T_ / BM, TWOD_ / BN, E_), 256, SMEM_BYTES>>>(b1, rw);
    gemm2_hk<<<dim3(T_ / BM, (H_ + BN - 1) / BN, 1), 256, SMEM_BYTES>>>(b2, rw, out);
}

// round 5
// speedup vs baseline: 2.5044x; 1.0029x over previous
#include <cuda_runtime.h>
#include <cuda_fp16.h>
#include <cstdint>

#define E_    8
#define T_    2048
#define H_    2880
#define D_    2880
#define TWOD_ 5760

#define BM 128
#define BN 128
#define BK 64                       // fp16 k per slab (128B rows, SW128 swizzle)
#define NS 4                        // cp.async stages
#define A_BYTES (BM * BK * 2)       // 16384
#define B_BYTES (BN * BK * 2)       // 16384
#define STAGE_BYTES (A_BYTES + B_BYTES)
#define SMEM_BYTES (NS * STAGE_BYTES)   // 131072

// ---------------- fp16 scratch ----------------
__device__ __align__(1024) __half g_w1t[(size_t)E_ * TWOD_ * H_];  // [e][n][k]
__device__ __align__(1024) __half g_w2t[(size_t)E_ * H_ * D_];     // [e][h][d]
__device__ __align__(1024) __half g_xh[(size_t)T_ * H_];           // [t][k]
__device__ __align__(1024) __half g_hid[(size_t)E_ * T_ * D_];     // [e][t][d]

// ---------------- PTX helpers (base ISA only) ----------------
__device__ __forceinline__ uint32_t smem_u32(const void* p) {
    uint32_t a;
    asm("{ .reg .u64 t; cvta.to.shared.u64 t, %1; cvt.u32.u64 %0, t; }" : "=r"(a) : "l"(p));
    return a;
}
__device__ __forceinline__ void cpa16(uint32_t dst, const void* src, int sz) {
    asm volatile("cp.async.cg.shared.global [%0], [%1], 16, %2;"
                 :: "r"(dst), "l"(src), "r"(sz) : "memory");
}
#define CP_COMMIT() asm volatile("cp.async.commit_group;" ::: "memory")
#define CP_WAIT(n)  asm volatile("cp.async.wait_group %0;" :: "n"(n) : "memory")

__device__ __forceinline__ void ldsm4(uint32_t (&r)[4], uint32_t addr) {
    asm volatile("ldmatrix.sync.aligned.m8n8.x4.shared.b16 {%0,%1,%2,%3}, [%4];"
                 : "=r"(r[0]), "=r"(r[1]), "=r"(r[2]), "=r"(r[3]) : "r"(addr));
}
__device__ __forceinline__ void mma16816(float c[4], const uint32_t a[4], const uint32_t b[2]) {
    asm volatile("mma.sync.aligned.m16n8k16.row.col.f32.f16.f16.f32 "
                 "{%0,%1,%2,%3}, {%4,%5,%6,%7}, {%8,%9}, {%0,%1,%2,%3};"
                 : "+f"(c[0]), "+f"(c[1]), "+f"(c[2]), "+f"(c[3])
                 : "r"(a[0]), "r"(a[1]), "r"(a[2]), "r"(a[3]), "r"(b[0]), "r"(b[1]));
}

// swizzled address within a [rows][64 halves] tile, 128B rows, Swizzle<3,4,3>
__device__ __forceinline__ uint32_t swaddr(uint32_t base, int row, int colbyte) {
    return base + row * 128 + (colbyte ^ ((row & 7) << 4));
}

// ---------------- prep kernels ----------------
__global__ void k_cvt_half(const float* __restrict__ src) {
    const float2* s2 = (const float2*)src;
    __half2* d2 = (__half2*)g_xh;
    size_t n = (size_t)T_ * H_ / 2;
    for (size_t i = (size_t)blockIdx.x * blockDim.x + threadIdx.x; i < n;
         i += (size_t)gridDim.x * blockDim.x) {
        float2 v = s2[i];
        d2[i] = __floats2half2_rn(v.x, v.y);
    }
}
// dst[z][c][r] = (half)src[z][r][c]; src [Z][R][C]; tiles 64(r) x 32(c)
__global__ void k_transpose_h(const float* __restrict__ src, __half* __restrict__ dst, int R, int C) {
    __shared__ float t[32][65];
    size_t zs = (size_t)blockIdx.z * R * C;
    int r0 = blockIdx.y * 64, c0 = blockIdx.x * 32;
    int tx = threadIdx.x, ty = threadIdx.y;
#pragma unroll
    for (int i = 0; i < 8; i++) {
        int r = ty + i * 8;
        t[tx][r] = src[zs + (size_t)(r0 + r) * C + c0 + tx];
    }
    __syncthreads();
    __half2* d2 = (__half2*)(dst + zs);
#pragma unroll
    for (int j = 0; j < 4; j++) {
        int c = ty + j * 8;
        d2[((size_t)(c0 + c) * R + r0) / 2 + tx] = __floats2half2_rn(t[c][2 * tx], t[c][2 * tx + 1]);
    }
}

// ============================================================================
// Mainloop pieces with register double-buffered fragments
// ============================================================================
struct Frag {
    float acc[2][8][4];
};

__device__ __forceinline__ void load_frags(uint32_t sA, uint32_t sB, int kk,
                                           uint32_t a[2][4], uint32_t b[8][2],
                                           int wm, int wn, int lane) {
    const int l7 = lane & 7, l15 = lane & 15;
    const int lb8 = (lane >> 3) & 1, lb16 = (lane >> 4) & 1;
#pragma unroll
    for (int i = 0; i < 2; i++) {
        uint32_t t[4];
        ldsm4(t, swaddr(sA, wm + i * 16 + l15, (kk << 5) | (lb16 << 4)));
        a[i][0] = t[0]; a[i][1] = t[1]; a[i][2] = t[2]; a[i][3] = t[3];
    }
#pragma unroll
    for (int jj = 0; jj < 4; jj++) {
        uint32_t t[4];
        ldsm4(t, swaddr(sB, wn + jj * 16 + l7 + (lb16 << 3), (kk << 5) | (lb8 << 4)));
        b[2 * jj][0] = t[0];     b[2 * jj][1] = t[1];
        b[2 * jj + 1][0] = t[2]; b[2 * jj + 1][1] = t[3];
    }
}

__device__ __forceinline__ void compute_slab(uint32_t sA, uint32_t sB, Frag& F,
                                             int wm, int wn, int lane) {
    uint32_t a[2][2][4], b[2][8][2];
    load_frags(sA, sB, 0, a[0], b[0], wm, wn, lane);
#pragma unroll
    for (int kk = 0; kk < BK / 16; kk++) {
        const int cur = kk & 1;
        if (kk + 1 < BK / 16)
            load_frags(sA, sB, kk + 1, a[cur ^ 1], b[cur ^ 1], wm, wn, lane);
#pragma unroll
        for (int i = 0; i < 2; i++)
#pragma unroll
            for (int j = 0; j < 8; j++)
                mma16816(F.acc[i][j], a[cur][i], b[cur][j]);
    }
}

// ============================================================================
// GEMM1: hid[e,t,d] = rw[t,e] * glu(X @ W1[e] + b1[e])
// ============================================================================
__global__ __launch_bounds__(256, 1)
void gemm1_hk(const float* __restrict__ b1, const float* __restrict__ rw) {
    extern __shared__ __align__(1024) char smem[];
    const uint32_t sb = smem_u32(smem);
    const int tid = threadIdx.x, lane = tid & 31, warp = tid >> 5;
    const int wm = (warp & 3) * 32, wn = (warp >> 2) * 64;
    const int m0 = blockIdx.x * BM, n0 = blockIdx.y * BN, e = blockIdx.z;

    Frag F;
#pragma unroll
    for (int i = 0; i < 2; i++)
#pragma unroll
        for (int j = 0; j < 8; j++)
#pragma unroll
            for (int q = 0; q < 4; q++) F.acc[i][j][q] = 0.f;

    const __half* Ab = g_xh + (size_t)m0 * H_;
    const __half* Bb = g_w1t + ((size_t)e * TWOD_ + n0) * H_;

    auto copy_slab = [&](int kt, int buf) {
        uint32_t sA = sb + buf * STAGE_BYTES, sB = sA + A_BYTES;
        const __half* ga = Ab + kt * BK;
        const __half* gb = Bb + kt * BK;
#pragma unroll
        for (int it = 0; it < 4; it++) {
            int ch = tid + it * 256;
            int r = ch >> 3, kc = ch & 7;
            cpa16(swaddr(sA, r, kc * 16), ga + (size_t)r * H_ + kc * 8, 16);
        }
#pragma unroll
        for (int it = 0; it < 4; it++) {
            int ch = tid + it * 256;
            int r = ch >> 3, kc = ch & 7;
            cpa16(swaddr(sB, r, kc * 16), gb + (size_t)r * H_ + kc * 8, 16);
        }
    };

    const int NKT = H_ / BK;  // 45
    copy_slab(0, 0); CP_COMMIT();
    copy_slab(1, 1); CP_COMMIT();
    copy_slab(2, 2); CP_COMMIT();
    int buf = 0;
    for (int kt = 0; kt < NKT; kt++) {
        CP_WAIT(2);
        __syncthreads();
        if (kt + 3 < NKT) copy_slab(kt + 3, (buf + 3) & (NS - 1));
        CP_COMMIT();
        compute_slab(sb + buf * STAGE_BYTES, sb + buf * STAGE_BYTES + A_BYTES, F, wm, wn, lane);
        buf = (buf + 1) & (NS - 1);
    }
    CP_WAIT(0);
    __syncthreads();

    // bias tile -> smem
    float* bsm = (float*)smem;
    for (int i = tid; i < BN; i += 256) bsm[i] = b1[(size_t)e * TWOD_ + n0 + i];
    __syncthreads();

    const int tig = lane & 3, gid = lane >> 2;
#pragma unroll
    for (int i = 0; i < 2; i++) {
#pragma unroll
        for (int s = 0; s < 2; s++) {
            int row = m0 + wm + i * 16 + s * 8 + gid;
            float rwv = rw[(size_t)row * E_ + e];
            __half* hd = g_hid + ((size_t)e * T_ + row) * D_ + (n0 >> 1);
#pragma unroll
            for (int j = 0; j < 8; j++) {
                int cl = wn + j * 8 + 2 * tig;
                float g = F.acc[i][j][2 * s]     + bsm[cl];
                float u = F.acc[i][j][2 * s + 1] + bsm[cl + 1];
                g = fminf(g, 7.0f);
                u = fminf(fmaxf(u, -7.0f), 7.0f);
                float sig = 1.0f / (1.0f + __expf(-1.702f * g));
                hd[cl >> 1] = __float2half_rn(rwv * (u + 1.0f) * (g * sig));
            }
        }
    }
}

// ============================================================================
// GEMM2: out[t,h] = sum_e hid[e,t,:] @ W2t[e][h,:] + sum_e rw[t,e]*b2[e,h]
// ============================================================================
__global__ __launch_bounds__(256, 1)
void gemm2_hk(const float* __restrict__ b2, const float* __restrict__ rw, float* __restrict__ out) {
    extern __shared__ __align__(1024) char smem[];
    const uint32_t sb = smem_u32(smem);
    const int tid = threadIdx.x, lane = tid & 31, warp = tid >> 5;
    const int wm = (warp & 3) * 32, wn = (warp >> 2) * 64;
    const int m0 = blockIdx.x * BM, n0 = blockIdx.y * BN;

    Frag F;
#pragma unroll
    for (int i = 0; i < 2; i++)
#pragma unroll
        for (int j = 0; j < 8; j++)
#pragma unroll
            for (int q = 0; q < 4; q++) F.acc[i][j][q] = 0.f;

    const int KPE = D_ / BK;      // 45
    const int NKT = E_ * KPE;     // 360

    auto copy_slab = [&](int kt, int buf) {
        int e = kt / KPE, kin = kt - e * KPE;
        uint32_t sA = sb + buf * STAGE_BYTES, sB = sA + A_BYTES;
        const __half* ga = g_hid + ((size_t)e * T_ + m0) * D_ + kin * BK;
        const __half* gb = g_w2t + ((size_t)e * H_ + n0) * D_ + kin * BK;
#pragma unroll
        for (int it = 0; it < 4; it++) {
            int ch = tid + it * 256;
            int r = ch >> 3, kc = ch & 7;
            cpa16(swaddr(sA, r, kc * 16), ga + (size_t)r * D_ + kc * 8, 16);
        }
#pragma unroll
        for (int it = 0; it < 4; it++) {
            int ch = tid + it * 256;
            int r = ch >> 3, kc = ch & 7;
            int ok = (n0 + r < H_) ? 16 : 0;     // tail rows zero-filled
            cpa16(swaddr(sB, r, kc * 16), gb + (size_t)r * D_ + kc * 8, ok);
        }
    };

    copy_slab(0, 0); CP_COMMIT();
    copy_slab(1, 1); CP_COMMIT();
    copy_slab(2, 2); CP_COMMIT();
    int buf = 0;
    for (int kt = 0; kt < NKT; kt++) {
        CP_WAIT(2);
        __syncthreads();
        if (kt + 3 < NKT) copy_slab(kt + 3, (buf + 3) & (NS - 1));
        CP_COMMIT();
        compute_slab(sb + buf * STAGE_BYTES, sb + buf * STAGE_BYTES + A_BYTES, F, wm, wn, lane);
        buf = (buf + 1) & (NS - 1);
    }
    CP_WAIT(0);
    __syncthreads();

    // b2 tile -> smem: [8][128]
    float* b2s = (float*)smem;
    for (int i = tid; i < E_ * BN; i += 256) {
        int ee = i >> 7, c = i & 127;
        int gc = n0 + c;
        b2s[i] = (gc < H_) ? b2[(size_t)ee * H_ + gc] : 0.f;
    }
    __syncthreads();

    const int tig = lane & 3, gid = lane >> 2;
    float rwr[2][2][E_];
#pragma unroll
    for (int i = 0; i < 2; i++)
#pragma unroll
        for (int s = 0; s < 2; s++) {
            int row = m0 + wm + i * 16 + s * 8 + gid;
            const float4* rp = (const float4*)(rw + (size_t)row * E_);
            float4 r0 = rp[0], r1 = rp[1];
            rwr[i][s][0] = r0.x; rwr[i][s][1] = r0.y; rwr[i][s][2] = r0.z; rwr[i][s][3] = r0.w;
            rwr[i][s][4] = r1.x; rwr[i][s][5] = r1.y; rwr[i][s][6] = r1.z; rwr[i][s][7] = r1.w;
        }

#pragma unroll
    for (int j = 0; j < 8; j++) {
        int cl = wn + j * 8 + 2 * tig;
        int gc = n0 + cl;
        if (gc < H_) {
            float bb0[E_], bb1[E_];
#pragma unroll
            for (int ee = 0; ee < E_; ee++) {
                bb0[ee] = b2s[ee * BN + cl];
                bb1[ee] = b2s[ee * BN + cl + 1];
            }
#pragma unroll
            for (int i = 0; i < 2; i++)
#pragma unroll
                for (int s = 0; s < 2; s++) {
                    int row = m0 + wm + i * 16 + s * 8 + gid;
                    float bs0 = 0.f, bs1 = 0.f;
#pragma unroll
                    for (int ee = 0; ee < E_; ee++) {
                        bs0 += rwr[i][s][ee] * bb0[ee];
                        bs1 += rwr[i][s][ee] * bb1[ee];
                    }
                    float2 v = make_float2(F.acc[i][j][2 * s] + bs0,
                                           F.acc[i][j][2 * s + 1] + bs1);
                    *(float2*)(out + (size_t)row * H_ + gc) = v;
                }
        }
    }
}

// ---------------- host ----------------
extern "C" void kernel_launch(void* const* d_in, const int* in_sizes, int n_in,
                              void* d_out, int out_size) {
    (void)in_sizes; (void)n_in; (void)out_size;
    const float* x  = (const float*)d_in[0];
    const float* rw = (const float*)d_in[1];
    const float* w1 = (const float*)d_in[2];
    const float* b1 = (const float*)d_in[3];
    const float* w2 = (const float*)d_in[4];
    const float* b2 = (const float*)d_in[5];
    float* out = (float*)d_out;

    void *p_w1t, *p_w2t;
    cudaGetSymbolAddress(&p_w1t, g_w1t);
    cudaGetSymbolAddress(&p_w2t, g_w2t);

    cudaFuncSetAttribute(gemm1_hk, cudaFuncAttributeMaxDynamicSharedMemorySize, SMEM_BYTES);
    cudaFuncSetAttribute(gemm2_hk, cudaFuncAttributeMaxDynamicSharedMemorySize, SMEM_BYTES);

    k_cvt_half<<<2048, 256>>>(x);
    k_transpose_h<<<dim3(TWOD_ / 32, H_ / 64, E_), dim3(32, 8)>>>(w1, (__half*)p_w1t, H_, TWOD_);
    k_transpose_h<<<dim3(H_ / 32, D_ / 64, E_), dim3(32, 8)>>>(w2, (__half*)p_w2t, D_, H_);

    gemm1_hk<<<dim3(T_ / BM, TWOD_ / BN, E_), 256, SMEM_BYTES>>>(b1, rw);
    gemm2_hk<<<dim3(T_ / BM, (H_ + BN - 1) / BN, 1), 256, SMEM_BYTES>>>(b2, rw, out);
}

// round 6
// speedup vs baseline: 3.0399x; 1.2138x over previous
#include <cuda_runtime.h>
#include <cuda_fp16.h>
#include <cstdint>

#define E_    8
#define T_    2048
#define H_    2880
#define D_    2880
#define TWOD_ 5760

#define BM 128
#define BN 128
#define BK 64                       // fp16 k per slab (128B rows, SW128 swizzle)
#define NS 3                        // cp.async stages
#define A_BYTES (BM * BK * 2)       // 16384
#define B_BYTES (BN * BK * 2)       // 16384
#define STAGE_BYTES (A_BYTES + B_BYTES)
#define SMEM_BYTES (NS * STAGE_BYTES)   // 98304 -> 2 CTAs/SM

// ---------------- fp16 scratch ----------------
__device__ __align__(1024) __half g_w1t[(size_t)E_ * TWOD_ * H_];  // [e][n][k]
__device__ __align__(1024) __half g_w2t[(size_t)E_ * H_ * D_];     // [e][h][d]
__device__ __align__(1024) __half g_xh[(size_t)T_ * H_];           // [t][k]
__device__ __align__(1024) __half g_hid[(size_t)E_ * T_ * D_];     // [e][t][d]

// ---------------- PTX helpers (base ISA only) ----------------
__device__ __forceinline__ uint32_t smem_u32(const void* p) {
    uint32_t a;
    asm("{ .reg .u64 t; cvta.to.shared.u64 t, %1; cvt.u32.u64 %0, t; }" : "=r"(a) : "l"(p));
    return a;
}
__device__ __forceinline__ void cpa16(uint32_t dst, const void* src, int sz) {
    asm volatile("cp.async.cg.shared.global [%0], [%1], 16, %2;"
                 :: "r"(dst), "l"(src), "r"(sz) : "memory");
}
#define CP_COMMIT() asm volatile("cp.async.commit_group;" ::: "memory")
#define CP_WAIT(n)  asm volatile("cp.async.wait_group %0;" :: "n"(n) : "memory")

__device__ __forceinline__ void ldsm4(uint32_t (&r)[4], uint32_t addr) {
    asm volatile("ldmatrix.sync.aligned.m8n8.x4.shared.b16 {%0,%1,%2,%3}, [%4];"
                 : "=r"(r[0]), "=r"(r[1]), "=r"(r[2]), "=r"(r[3]) : "r"(addr));
}
__device__ __forceinline__ void mma16816(float c[4], const uint32_t a[4], const uint32_t b[2]) {
    asm volatile("mma.sync.aligned.m16n8k16.row.col.f32.f16.f16.f32 "
                 "{%0,%1,%2,%3}, {%4,%5,%6,%7}, {%8,%9}, {%0,%1,%2,%3};"
                 : "+f"(c[0]), "+f"(c[1]), "+f"(c[2]), "+f"(c[3])
                 : "r"(a[0]), "r"(a[1]), "r"(a[2]), "r"(a[3]), "r"(b[0]), "r"(b[1]));
}

// swizzled address within a [rows][64 halves] tile, 128B rows, Swizzle<3,4,3>
__device__ __forceinline__ uint32_t swaddr(uint32_t base, int row, int colbyte) {
    return base + row * 128 + (colbyte ^ ((row & 7) << 4));
}

// ---------------- prep kernels ----------------
__global__ void k_cvt_half(const float* __restrict__ src) {
    const float2* s2 = (const float2*)src;
    __half2* d2 = (__half2*)g_xh;
    size_t n = (size_t)T_ * H_ / 2;
    for (size_t i = (size_t)blockIdx.x * blockDim.x + threadIdx.x; i < n;
         i += (size_t)gridDim.x * blockDim.x) {
        float2 v = s2[i];
        d2[i] = __floats2half2_rn(v.x, v.y);
    }
}
// dst[z][c][r] = (half)src[z][r][c]; src [Z][R][C]; tiles 64(r) x 32(c)
__global__ void k_transpose_h(const float* __restrict__ src, __half* __restrict__ dst, int R, int C) {
    __shared__ float t[32][65];
    size_t zs = (size_t)blockIdx.z * R * C;
    int r0 = blockIdx.y * 64, c0 = blockIdx.x * 32;
    int tx = threadIdx.x, ty = threadIdx.y;
#pragma unroll
    for (int i = 0; i < 8; i++) {
        int r = ty + i * 8;
        t[tx][r] = src[zs + (size_t)(r0 + r) * C + c0 + tx];
    }
    __syncthreads();
    __half2* d2 = (__half2*)(dst + zs);
#pragma unroll
    for (int j = 0; j < 4; j++) {
        int c = ty + j * 8;
        d2[((size_t)(c0 + c) * R + r0) / 2 + tx] = __floats2half2_rn(t[c][2 * tx], t[c][2 * tx + 1]);
    }
}

// ============================================================================
// Mainloop compute (single-buffered fragments; ptxas schedules)
// ============================================================================
struct Frag {
    float acc[2][8][4];
};

__device__ __forceinline__ void compute_slab(uint32_t sA, uint32_t sB, Frag& F,
                                             int wm, int wn, int lane) {
    const int l7 = lane & 7, l15 = lane & 15;
    const int lb8 = (lane >> 3) & 1, lb16 = (lane >> 4) & 1;
#pragma unroll
    for (int kk = 0; kk < BK / 16; kk++) {
        uint32_t a[2][4];
#pragma unroll
        for (int i = 0; i < 2; i++) {
            int row = wm + i * 16 + l15;
            ldsm4(a[i], swaddr(sA, row, (kk << 5) | (lb16 << 4)));
        }
        uint32_t b[8][2];
#pragma unroll
        for (int jj = 0; jj < 4; jj++) {
            int row = wn + jj * 16 + l7 + (lb16 << 3);
            uint32_t t[4];
            ldsm4(t, swaddr(sB, row, (kk << 5) | (lb8 << 4)));
            b[2 * jj][0] = t[0];     b[2 * jj][1] = t[1];
            b[2 * jj + 1][0] = t[2]; b[2 * jj + 1][1] = t[3];
        }
#pragma unroll
        for (int i = 0; i < 2; i++)
#pragma unroll
            for (int j = 0; j < 8; j++)
                mma16816(F.acc[i][j], a[i], b[j]);
    }
}

// ============================================================================
// GEMM1: hid[e,t,d] = rw[t,e] * glu(X @ W1[e] + b1[e])
// ============================================================================
__global__ __launch_bounds__(256, 2)
void gemm1_hk(const float* __restrict__ b1, const float* __restrict__ rw) {
    extern __shared__ __align__(1024) char smem[];
    const uint32_t sb = smem_u32(smem);
    const int tid = threadIdx.x, lane = tid & 31, warp = tid >> 5;
    const int wm = (warp & 3) * 32, wn = (warp >> 2) * 64;
    const int m0 = blockIdx.x * BM, n0 = blockIdx.y * BN, e = blockIdx.z;

    Frag F;
#pragma unroll
    for (int i = 0; i < 2; i++)
#pragma unroll
        for (int j = 0; j < 8; j++)
#pragma unroll
            for (int q = 0; q < 4; q++) F.acc[i][j][q] = 0.f;

    const __half* Ab = g_xh + (size_t)m0 * H_;
    const __half* Bb = g_w1t + ((size_t)e * TWOD_ + n0) * H_;

    auto copy_slab = [&](int kt, int buf) {
        uint32_t sA = sb + buf * STAGE_BYTES, sB = sA + A_BYTES;
        const __half* ga = Ab + kt * BK;
        const __half* gb = Bb + kt * BK;
#pragma unroll
        for (int it = 0; it < 4; it++) {
            int ch = tid + it * 256;
            int r = ch >> 3, kc = ch & 7;
            cpa16(swaddr(sA, r, kc * 16), ga + (size_t)r * H_ + kc * 8, 16);
        }
#pragma unroll
        for (int it = 0; it < 4; it++) {
            int ch = tid + it * 256;
            int r = ch >> 3, kc = ch & 7;
            cpa16(swaddr(sB, r, kc * 16), gb + (size_t)r * H_ + kc * 8, 16);
        }
    };

    const int NKT = H_ / BK;  // 45
    copy_slab(0, 0); CP_COMMIT();
    copy_slab(1, 1); CP_COMMIT();
    int buf = 0;
    for (int kt = 0; kt < NKT; kt++) {
        CP_WAIT(1);
        __syncthreads();
        if (kt + 2 < NKT) copy_slab(kt + 2, (buf + 2) % NS);
        CP_COMMIT();
        compute_slab(sb + buf * STAGE_BYTES, sb + buf * STAGE_BYTES + A_BYTES, F, wm, wn, lane);
        buf = (buf == NS - 1) ? 0 : buf + 1;
    }
    CP_WAIT(0);
    __syncthreads();

    // bias tile -> smem
    float* bsm = (float*)smem;
    for (int i = tid; i < BN; i += 256) bsm[i] = b1[(size_t)e * TWOD_ + n0 + i];
    __syncthreads();

    const int tig = lane & 3, gid = lane >> 2;
#pragma unroll
    for (int i = 0; i < 2; i++) {
#pragma unroll
        for (int s = 0; s < 2; s++) {
            int row = m0 + wm + i * 16 + s * 8 + gid;
            float rwv = rw[(size_t)row * E_ + e];
            __half* hd = g_hid + ((size_t)e * T_ + row) * D_ + (n0 >> 1);
#pragma unroll
            for (int j = 0; j < 8; j++) {
                int cl = wn + j * 8 + 2 * tig;
                float g = F.acc[i][j][2 * s]     + bsm[cl];
                float u = F.acc[i][j][2 * s + 1] + bsm[cl + 1];
                g = fminf(g, 7.0f);
                u = fminf(fmaxf(u, -7.0f), 7.0f);
                float sig = 1.0f / (1.0f + __expf(-1.702f * g));
                hd[cl >> 1] = __float2half_rn(rwv * (u + 1.0f) * (g * sig));
            }
        }
    }
}

// ============================================================================
// GEMM2: out[t,h] = sum_e hid[e,t,:] @ W2t[e][h,:] + sum_e rw[t,e]*b2[e,h]
// ============================================================================
__global__ __launch_bounds__(256, 2)
void gemm2_hk(const float* __restrict__ b2, const float* __restrict__ rw, float* __restrict__ out) {
    extern __shared__ __align__(1024) char smem[];
    const uint32_t sb = smem_u32(smem);
    const int tid = threadIdx.x, lane = tid & 31, warp = tid >> 5;
    const int wm = (warp & 3) * 32, wn = (warp >> 2) * 64;
    const int m0 = blockIdx.x * BM, n0 = blockIdx.y * BN;

    Frag F;
#pragma unroll
    for (int i = 0; i < 2; i++)
#pragma unroll
        for (int j = 0; j < 8; j++)
#pragma unroll
            for (int q = 0; q < 4; q++) F.acc[i][j][q] = 0.f;

    const int KPE = D_ / BK;      // 45
    const int NKT = E_ * KPE;     // 360

    auto copy_slab = [&](int kt, int buf) {
        int e = kt / KPE, kin = kt - e * KPE;
        uint32_t sA = sb + buf * STAGE_BYTES, sB = sA + A_BYTES;
        const __half* ga = g_hid + ((size_t)e * T_ + m0) * D_ + kin * BK;
        const __half* gb = g_w2t + ((size_t)e * H_ + n0) * D_ + kin * BK;
#pragma unroll
        for (int it = 0; it < 4; it++) {
            int ch = tid + it * 256;
            int r = ch >> 3, kc = ch & 7;
            cpa16(swaddr(sA, r, kc * 16), ga + (size_t)r * D_ + kc * 8, 16);
        }
#pragma unroll
        for (int it = 0; it < 4; it++) {
            int ch = tid + it * 256;
            int r = ch >> 3, kc = ch & 7;
            int ok = (n0 + r < H_) ? 16 : 0;     // tail rows zero-filled
            cpa16(swaddr(sB, r, kc * 16), gb + (size_t)r * D_ + kc * 8, ok);
        }
    };

    copy_slab(0, 0); CP_COMMIT();
    copy_slab(1, 1); CP_COMMIT();
    int buf = 0;
    for (int kt = 0; kt < NKT; kt++) {
        CP_WAIT(1);
        __syncthreads();
        if (kt + 2 < NKT) copy_slab(kt + 2, (buf + 2) % NS);
        CP_COMMIT();
        compute_slab(sb + buf * STAGE_BYTES, sb + buf * STAGE_BYTES + A_BYTES, F, wm, wn, lane);
        buf = (buf == NS - 1) ? 0 : buf + 1;
    }
    CP_WAIT(0);
    __syncthreads();

    // b2 tile -> smem: [8][128]
    float* b2s = (float*)smem;
    for (int i = tid; i < E_ * BN; i += 256) {
        int ee = i >> 7, c = i & 127;
        int gc = n0 + c;
        b2s[i] = (gc < H_) ? b2[(size_t)ee * H_ + gc] : 0.f;
    }
    __syncthreads();

    const int tig = lane & 3, gid = lane >> 2;
#pragma unroll
    for (int j = 0; j < 8; j++) {
        int cl = wn + j * 8 + 2 * tig;
        int gc = n0 + cl;
        if (gc < H_) {
            float bb0[E_], bb1[E_];
#pragma unroll
            for (int ee = 0; ee < E_; ee++) {
                bb0[ee] = b2s[ee * BN + cl];
                bb1[ee] = b2s[ee * BN + cl + 1];
            }
#pragma unroll
            for (int i = 0; i < 2; i++)
#pragma unroll
                for (int s = 0; s < 2; s++) {
                    int row = m0 + wm + i * 16 + s * 8 + gid;
                    const float4* rp = (const float4*)(rw + (size_t)row * E_);
                    float4 r0 = rp[0], r1 = rp[1];
                    float bs0 = r0.x * bb0[0] + r0.y * bb0[1] + r0.z * bb0[2] + r0.w * bb0[3]
                              + r1.x * bb0[4] + r1.y * bb0[5] + r1.z * bb0[6] + r1.w * bb0[7];
                    float bs1 = r0.x * bb1[0] + r0.y * bb1[1] + r0.z * bb1[2] + r0.w * bb1[3]
                              + r1.x * bb1[4] + r1.y * bb1[5] + r1.z * bb1[6] + r1.w * bb1[7];
                    float2 v = make_float2(F.acc[i][j][2 * s] + bs0,
                                           F.acc[i][j][2 * s + 1] + bs1);
                    *(float2*)(out + (size_t)row * H_ + gc) = v;
                }
        }
    }
}

// ---------------- host ----------------
extern "C" void kernel_launch(void* const* d_in, const int* in_sizes, int n_in,
                              void* d_out, int out_size) {
    (void)in_sizes; (void)n_in; (void)out_size;
    const float* x  = (const float*)d_in[0];
    const float* rw = (const float*)d_in[1];
    const float* w1 = (const float*)d_in[2];
    const float* b1 = (const float*)d_in[3];
    const float* w2 = (const float*)d_in[4];
    const float* b2 = (const float*)d_in[5];
    float* out = (float*)d_out;

    void *p_w1t, *p_w2t;
    cudaGetSymbolAddress(&p_w1t, g_w1t);
    cudaGetSymbolAddress(&p_w2t, g_w2t);

    cudaFuncSetAttribute(gemm1_hk, cudaFuncAttributeMaxDynamicSharedMemorySize, SMEM_BYTES);
    cudaFuncSetAttribute(gemm2_hk, cudaFuncAttributeMaxDynamicSharedMemorySize, SMEM_BYTES);

    k_cvt_half<<<2048, 256>>>(x);
    k_transpose_h<<<dim3(TWOD_ / 32, H_ / 64, E_), dim3(32, 8)>>>(w1, (__half*)p_w1t, H_, TWOD_);
    k_transpose_h<<<dim3(H_ / 32, D_ / 64, E_), dim3(32, 8)>>>(w2, (__half*)p_w2t, D_, H_);

    gemm1_hk<<<dim3(T_ / BM, TWOD_ / BN, E_), 256, SMEM_BYTES>>>(b1, rw);
    gemm2_hk<<<dim3(T_ / BM, (H_ + BN - 1) / BN, 1), 256, SMEM_BYTES>>>(b2, rw, out);
}

// round 7
// speedup vs baseline: 3.2082x; 1.0554x over previous
#include <cuda_runtime.h>
#include <cuda_fp16.h>
#include <cstdint>

#define E_    8
#define T_    2048
#define H_    2880
#define D_    2880
#define TWOD_ 5760
#define SPLITK 4
#define EPS   (E_ / SPLITK)         // experts per split = 2

#define BM 128
#define BN 128
#define BK 64                       // fp16 k per slab (128B rows, SW128 swizzle)
#define NS 3                        // cp.async stages
#define A_BYTES (BM * BK * 2)       // 16384
#define B_BYTES (BN * BK * 2)       // 16384
#define STAGE_BYTES (A_BYTES + B_BYTES)
#define SMEM_BYTES (NS * STAGE_BYTES)   // 98304 -> 2 CTAs/SM

// ---------------- scratch ----------------
__device__ __align__(1024) __half g_w1t[(size_t)E_ * TWOD_ * H_];  // [e][n][k]
__device__ __align__(1024) __half g_w2t[(size_t)E_ * H_ * D_];     // [e][h][d]
__device__ __align__(1024) __half g_xh[(size_t)T_ * H_];           // [t][k]
__device__ __align__(1024) __half g_hid[(size_t)E_ * T_ * D_];     // [e][t][d]
__device__ __align__(1024) float  g_part[(size_t)SPLITK * T_ * H_]; // split-k partials

// ---------------- PTX helpers (base ISA only) ----------------
__device__ __forceinline__ uint32_t smem_u32(const void* p) {
    uint32_t a;
    asm("{ .reg .u64 t; cvta.to.shared.u64 t, %1; cvt.u32.u64 %0, t; }" : "=r"(a) : "l"(p));
    return a;
}
__device__ __forceinline__ void cpa16(uint32_t dst, const void* src, int sz) {
    asm volatile("cp.async.cg.shared.global [%0], [%1], 16, %2;"
                 :: "r"(dst), "l"(src), "r"(sz) : "memory");
}
#define CP_COMMIT() asm volatile("cp.async.commit_group;" ::: "memory")
#define CP_WAIT(n)  asm volatile("cp.async.wait_group %0;" :: "n"(n) : "memory")

__device__ __forceinline__ void ldsm4(uint32_t (&r)[4], uint32_t addr) {
    asm volatile("ldmatrix.sync.aligned.m8n8.x4.shared.b16 {%0,%1,%2,%3}, [%4];"
                 : "=r"(r[0]), "=r"(r[1]), "=r"(r[2]), "=r"(r[3]) : "r"(addr));
}
__device__ __forceinline__ void mma16816(float c[4], const uint32_t a[4], const uint32_t b[2]) {
    asm volatile("mma.sync.aligned.m16n8k16.row.col.f32.f16.f16.f32 "
                 "{%0,%1,%2,%3}, {%4,%5,%6,%7}, {%8,%9}, {%0,%1,%2,%3};"
                 : "+f"(c[0]), "+f"(c[1]), "+f"(c[2]), "+f"(c[3])
                 : "r"(a[0]), "r"(a[1]), "r"(a[2]), "r"(a[3]), "r"(b[0]), "r"(b[1]));
}

// swizzled address within a [rows][64 halves] tile, 128B rows, Swizzle<3,4,3>
__device__ __forceinline__ uint32_t swaddr(uint32_t base, int row, int colbyte) {
    return base + row * 128 + (colbyte ^ ((row & 7) << 4));
}

// ---------------- prep kernels ----------------
__global__ void k_cvt_half(const float* __restrict__ src) {
    const float2* s2 = (const float2*)src;
    __half2* d2 = (__half2*)g_xh;
    size_t n = (size_t)T_ * H_ / 2;
    for (size_t i = (size_t)blockIdx.x * blockDim.x + threadIdx.x; i < n;
         i += (size_t)gridDim.x * blockDim.x) {
        float2 v = s2[i];
        d2[i] = __floats2half2_rn(v.x, v.y);
    }
}
// dst[z][c][r] = (half)src[z][r][c]; src [Z][R][C]; tiles 64(r) x 32(c)
__global__ void k_transpose_h(const float* __restrict__ src, __half* __restrict__ dst, int R, int C) {
    __shared__ float t[32][65];
    size_t zs = (size_t)blockIdx.z * R * C;
    int r0 = blockIdx.y * 64, c0 = blockIdx.x * 32;
    int tx = threadIdx.x, ty = threadIdx.y;
#pragma unroll
    for (int i = 0; i < 8; i++) {
        int r = ty + i * 8;
        t[tx][r] = src[zs + (size_t)(r0 + r) * C + c0 + tx];
    }
    __syncthreads();
    __half2* d2 = (__half2*)(dst + zs);
#pragma unroll
    for (int j = 0; j < 4; j++) {
        int c = ty + j * 8;
        d2[((size_t)(c0 + c) * R + r0) / 2 + tx] = __floats2half2_rn(t[c][2 * tx], t[c][2 * tx + 1]);
    }
}

// ============================================================================
// Mainloop compute
// ============================================================================
struct Frag {
    float acc[2][8][4];
};

__device__ __forceinline__ void compute_slab(uint32_t sA, uint32_t sB, Frag& F,
                                             int wm, int wn, int lane) {
    const int l7 = lane & 7, l15 = lane & 15;
    const int lb8 = (lane >> 3) & 1, lb16 = (lane >> 4) & 1;
#pragma unroll
    for (int kk = 0; kk < BK / 16; kk++) {
        uint32_t a[2][4];
#pragma unroll
        for (int i = 0; i < 2; i++) {
            int row = wm + i * 16 + l15;
            ldsm4(a[i], swaddr(sA, row, (kk << 5) | (lb16 << 4)));
        }
        uint32_t b[8][2];
#pragma unroll
        for (int jj = 0; jj < 4; jj++) {
            int row = wn + jj * 16 + l7 + (lb16 << 3);
            uint32_t t[4];
            ldsm4(t, swaddr(sB, row, (kk << 5) | (lb8 << 4)));
            b[2 * jj][0] = t[0];     b[2 * jj][1] = t[1];
            b[2 * jj + 1][0] = t[2]; b[2 * jj + 1][1] = t[3];
        }
#pragma unroll
        for (int i = 0; i < 2; i++)
#pragma unroll
            for (int j = 0; j < 8; j++)
                mma16816(F.acc[i][j], a[i], b[j]);
    }
}

// ============================================================================
// GEMM1: hid[e,t,d] = rw[t,e] * glu(X @ W1[e] + b1[e])
// ============================================================================
__global__ __launch_bounds__(256, 2)
void gemm1_hk(const float* __restrict__ b1, const float* __restrict__ rw) {
    extern __shared__ __align__(1024) char smem[];
    const uint32_t sb = smem_u32(smem);
    const int tid = threadIdx.x, lane = tid & 31, warp = tid >> 5;
    const int wm = (warp & 3) * 32, wn = (warp >> 2) * 64;
    const int m0 = blockIdx.x * BM, n0 = blockIdx.y * BN, e = blockIdx.z;

    Frag F;
#pragma unroll
    for (int i = 0; i < 2; i++)
#pragma unroll
        for (int j = 0; j < 8; j++)
#pragma unroll
            for (int q = 0; q < 4; q++) F.acc[i][j][q] = 0.f;

    const __half* Ab = g_xh + (size_t)m0 * H_;
    const __half* Bb = g_w1t + ((size_t)e * TWOD_ + n0) * H_;

    auto copy_slab = [&](int kt, int buf) {
        uint32_t sA = sb + buf * STAGE_BYTES, sB = sA + A_BYTES;
        const __half* ga = Ab + kt * BK;
        const __half* gb = Bb + kt * BK;
#pragma unroll
        for (int it = 0; it < 4; it++) {
            int ch = tid + it * 256;
            int r = ch >> 3, kc = ch & 7;
            cpa16(swaddr(sA, r, kc * 16), ga + (size_t)r * H_ + kc * 8, 16);
        }
#pragma unroll
        for (int it = 0; it < 4; it++) {
            int ch = tid + it * 256;
            int r = ch >> 3, kc = ch & 7;
            cpa16(swaddr(sB, r, kc * 16), gb + (size_t)r * H_ + kc * 8, 16);
        }
    };

    const int NKT = H_ / BK;  // 45
    copy_slab(0, 0); CP_COMMIT();
    copy_slab(1, 1); CP_COMMIT();
    int buf = 0;
    for (int kt = 0; kt < NKT; kt++) {
        CP_WAIT(1);
        __syncthreads();
        if (kt + 2 < NKT) copy_slab(kt + 2, (buf + 2) % NS);
        CP_COMMIT();
        compute_slab(sb + buf * STAGE_BYTES, sb + buf * STAGE_BYTES + A_BYTES, F, wm, wn, lane);
        buf = (buf == NS - 1) ? 0 : buf + 1;
    }
    CP_WAIT(0);
    __syncthreads();

    // bias tile -> smem
    float* bsm = (float*)smem;
    for (int i = tid; i < BN; i += 256) bsm[i] = b1[(size_t)e * TWOD_ + n0 + i];
    __syncthreads();

    const int tig = lane & 3, gid = lane >> 2;
#pragma unroll
    for (int i = 0; i < 2; i++) {
#pragma unroll
        for (int s = 0; s < 2; s++) {
            int row = m0 + wm + i * 16 + s * 8 + gid;
            float rwv = rw[(size_t)row * E_ + e];
            __half* hd = g_hid + ((size_t)e * T_ + row) * D_ + (n0 >> 1);
#pragma unroll
            for (int j = 0; j < 8; j++) {
                int cl = wn + j * 8 + 2 * tig;
                float g = F.acc[i][j][2 * s]     + bsm[cl];
                float u = F.acc[i][j][2 * s + 1] + bsm[cl + 1];
                g = fminf(g, 7.0f);
                u = fminf(fmaxf(u, -7.0f), 7.0f);
                float sig = 1.0f / (1.0f + __expf(-1.702f * g));
                hd[cl >> 1] = __float2half_rn(rwv * (u + 1.0f) * (g * sig));
            }
        }
    }
}

// ============================================================================
// GEMM2 (split-K over experts): g_part[z][t,h] = sum_{e in split z} hid@W2t
// ============================================================================
__global__ __launch_bounds__(256, 2)
void gemm2_hk() {
    extern __shared__ __align__(1024) char smem[];
    const uint32_t sb = smem_u32(smem);
    const int tid = threadIdx.x, lane = tid & 31, warp = tid >> 5;
    const int wm = (warp & 3) * 32, wn = (warp >> 2) * 64;
    const int m0 = blockIdx.x * BM, n0 = blockIdx.y * BN, z = blockIdx.z;

    Frag F;
#pragma unroll
    for (int i = 0; i < 2; i++)
#pragma unroll
        for (int j = 0; j < 8; j++)
#pragma unroll
            for (int q = 0; q < 4; q++) F.acc[i][j][q] = 0.f;

    const int KPE = D_ / BK;        // 45
    const int NKT = EPS * KPE;      // 90

    auto copy_slab = [&](int kt, int buf) {
        int e = z * EPS + kt / KPE, kin = kt % KPE;
        uint32_t sA = sb + buf * STAGE_BYTES, sB = sA + A_BYTES;
        const __half* ga = g_hid + ((size_t)e * T_ + m0) * D_ + kin * BK;
        const __half* gb = g_w2t + ((size_t)e * H_ + n0) * D_ + kin * BK;
#pragma unroll
        for (int it = 0; it < 4; it++) {
            int ch = tid + it * 256;
            int r = ch >> 3, kc = ch & 7;
            cpa16(swaddr(sA, r, kc * 16), ga + (size_t)r * D_ + kc * 8, 16);
        }
#pragma unroll
        for (int it = 0; it < 4; it++) {
            int ch = tid + it * 256;
            int r = ch >> 3, kc = ch & 7;
            int ok = (n0 + r < H_) ? 16 : 0;     // tail rows zero-filled
            cpa16(swaddr(sB, r, kc * 16), gb + (size_t)r * D_ + kc * 8, ok);
        }
    };

    copy_slab(0, 0); CP_COMMIT();
    copy_slab(1, 1); CP_COMMIT();
    int buf = 0;
    for (int kt = 0; kt < NKT; kt++) {
        CP_WAIT(1);
        __syncthreads();
        if (kt + 2 < NKT) copy_slab(kt + 2, (buf + 2) % NS);
        CP_COMMIT();
        compute_slab(sb + buf * STAGE_BYTES, sb + buf * STAGE_BYTES + A_BYTES, F, wm, wn, lane);
        buf = (buf == NS - 1) ? 0 : buf + 1;
    }

    const int tig = lane & 3, gid = lane >> 2;
    float* pd = g_part + (size_t)z * T_ * H_;
#pragma unroll
    for (int j = 0; j < 8; j++) {
        int cl = wn + j * 8 + 2 * tig;
        int gc = n0 + cl;
        if (gc < H_) {
#pragma unroll
            for (int i = 0; i < 2; i++)
#pragma unroll
                for (int s = 0; s < 2; s++) {
                    int row = m0 + wm + i * 16 + s * 8 + gid;
                    float2 v = make_float2(F.acc[i][j][2 * s], F.acc[i][j][2 * s + 1]);
                    *(float2*)(pd + (size_t)row * H_ + gc) = v;
                }
        }
    }
}

// ============================================================================
// Reduce: out = sum_z g_part[z] + sum_e rw[t,e]*b2[e,h]
// ============================================================================
__global__ __launch_bounds__(256)
void k_reduce(const float* __restrict__ rw, const float* __restrict__ b2,
              float* __restrict__ out) {
    size_t i4 = (size_t)blockIdx.x * blockDim.x + threadIdx.x;   // float4 index
    const size_t N4 = (size_t)T_ * H_ / 4;
    if (i4 >= N4) return;
    size_t idx = i4 * 4;
    int t = (int)(idx / H_), h = (int)(idx % H_);   // H_%4==0 -> same row

    const float4* p0 = (const float4*)g_part;
    float4 a0 = p0[i4];
    float4 a1 = p0[N4 + i4];
    float4 a2 = p0[2 * N4 + i4];
    float4 a3 = p0[3 * N4 + i4];
    float4 acc = make_float4(a0.x + a1.x + a2.x + a3.x,
                             a0.y + a1.y + a2.y + a3.y,
                             a0.z + a1.z + a2.z + a3.z,
                             a0.w + a1.w + a2.w + a3.w);

    const float4* rp = (const float4*)(rw + (size_t)t * E_);
    float4 r0 = rp[0], r1 = rp[1];
    float rr[E_] = {r0.x, r0.y, r0.z, r0.w, r1.x, r1.y, r1.z, r1.w};
#pragma unroll
    for (int e = 0; e < E_; e++) {
        float4 bb = *(const float4*)(b2 + (size_t)e * H_ + h);
        acc.x += rr[e] * bb.x;
        acc.y += rr[e] * bb.y;
        acc.z += rr[e] * bb.z;
        acc.w += rr[e] * bb.w;
    }
    ((float4*)out)[i4] = acc;
}

// ---------------- host ----------------
extern "C" void kernel_launch(void* const* d_in, const int* in_sizes, int n_in,
                              void* d_out, int out_size) {
    (void)in_sizes; (void)n_in; (void)out_size;
    const float* x  = (const float*)d_in[0];
    const float* rw = (const float*)d_in[1];
    const float* w1 = (const float*)d_in[2];
    const float* b1 = (const float*)d_in[3];
    const float* w2 = (const float*)d_in[4];
    const float* b2 = (const float*)d_in[5];
    float* out = (float*)d_out;

    void *p_w1t, *p_w2t;
    cudaGetSymbolAddress(&p_w1t, g_w1t);
    cudaGetSymbolAddress(&p_w2t, g_w2t);

    cudaFuncSetAttribute(gemm1_hk, cudaFuncAttributeMaxDynamicSharedMemorySize, SMEM_BYTES);
    cudaFuncSetAttribute(gemm2_hk, cudaFuncAttributeMaxDynamicSharedMemorySize, SMEM_BYTES);

    k_cvt_half<<<2048, 256>>>(x);
    k_transpose_h<<<dim3(TWOD_ / 32, H_ / 64, E_), dim3(32, 8)>>>(w1, (__half*)p_w1t, H_, TWOD_);
    k_transpose_h<<<dim3(H_ / 32, D_ / 64, E_), dim3(32, 8)>>>(w2, (__half*)p_w2t, D_, H_);

    gemm1_hk<<<dim3(T_ / BM, TWOD_ / BN, E_), 256, SMEM_BYTES>>>(b1, rw);
    gemm2_hk<<<dim3(T_ / BM, (H_ + BN - 1) / BN, SPLITK), 256, SMEM_BYTES>>>();
    k_reduce<<<(T_ * H_ / 4 + 255) / 256, 256>>>(rw, b2, out);
}

// round 9
// speedup vs baseline: 3.4779x; 1.0841x over previous
#include <cuda_runtime.h>
#include <cuda_fp16.h>
#include <cstdint>

#define E_    8
#define T_    2048
#define H_    2880
#define D_    2880
#define TWOD_ 5760
#define SPLITK 4
#define EPS   (E_ / SPLITK)         // experts per split = 2

#define BM 128
#define BN 128
#define BK 64                       // fp16 k per slab (128B rows, SW128 swizzle)
#define NS 3                        // cp.async stages
#define A_BYTES (BM * BK * 2)       // 16384
#define B_BYTES (BN * BK * 2)       // 16384
#define STAGE_BYTES (A_BYTES + B_BYTES)
#define SMEM_BYTES (NS * STAGE_BYTES)   // 98304 -> 2 CTAs/SM

// ---------------- scratch ----------------
__device__ __align__(1024) __half g_w1t[(size_t)E_ * TWOD_ * H_];  // [e][n][k]
__device__ __align__(1024) __half g_w2t[(size_t)E_ * H_ * D_];     // [e][h][d]
__device__ __align__(1024) __half g_xh[(size_t)T_ * H_];           // [t][k]
__device__ __align__(1024) __half g_hid[(size_t)E_ * T_ * D_];     // [e][t][d]
__device__ __align__(1024) float  g_part[(size_t)SPLITK * T_ * H_]; // split-k partials

// ---------------- PTX helpers (base ISA only) ----------------
__device__ __forceinline__ uint32_t smem_u32(const void* p) {
    uint32_t a;
    asm("{ .reg .u64 t; cvta.to.shared.u64 t, %1; cvt.u32.u64 %0, t; }" : "=r"(a) : "l"(p));
    return a;
}
__device__ __forceinline__ void cpa16(uint32_t dst, const void* src, int sz) {
    asm volatile("cp.async.cg.shared.global [%0], [%1], 16, %2;"
                 :: "r"(dst), "l"(src), "r"(sz) : "memory");
}
#define CP_COMMIT() asm volatile("cp.async.commit_group;" ::: "memory")
#define CP_WAIT(n)  asm volatile("cp.async.wait_group %0;" :: "n"(n) : "memory")

__device__ __forceinline__ void ldsm4(uint32_t (&r)[4], uint32_t addr) {
    asm volatile("ldmatrix.sync.aligned.m8n8.x4.shared.b16 {%0,%1,%2,%3}, [%4];"
                 : "=r"(r[0]), "=r"(r[1]), "=r"(r[2]), "=r"(r[3]) : "r"(addr));
}
__device__ __forceinline__ void mma16816(float c[4], const uint32_t a[4], const uint32_t b[2]) {
    asm volatile("mma.sync.aligned.m16n8k16.row.col.f32.f16.f16.f32 "
                 "{%0,%1,%2,%3}, {%4,%5,%6,%7}, {%8,%9}, {%0,%1,%2,%3};"
                 : "+f"(c[0]), "+f"(c[1]), "+f"(c[2]), "+f"(c[3])
                 : "r"(a[0]), "r"(a[1]), "r"(a[2]), "r"(a[3]), "r"(b[0]), "r"(b[1]));
}

// swizzled address within a [rows][64 halves] tile, 128B rows, Swizzle<3,4,3>
__device__ __forceinline__ uint32_t swaddr(uint32_t base, int row, int colbyte) {
    return base + row * 128 + (colbyte ^ ((row & 7) << 4));
}

// ---------------- prep kernels ----------------
__global__ void k_cvt_half(const float* __restrict__ src) {
    const float2* s2 = (const float2*)src;
    __half2* d2 = (__half2*)g_xh;
    size_t n = (size_t)T_ * H_ / 2;
    for (size_t i = (size_t)blockIdx.x * blockDim.x + threadIdx.x; i < n;
         i += (size_t)gridDim.x * blockDim.x) {
        float2 v = s2[i];
        d2[i] = __floats2half2_rn(v.x, v.y);
    }
}
// dst[z][c][r] = (half)src[z][r][c]; src [Z][R][C]; tiles 64(r) x 32(c)
__global__ void k_transpose_h(const float* __restrict__ src, __half* __restrict__ dst, int R, int C) {
    __shared__ float t[32][65];
    size_t zs = (size_t)blockIdx.z * R * C;
    int r0 = blockIdx.y * 64, c0 = blockIdx.x * 32;
    int tx = threadIdx.x, ty = threadIdx.y;
#pragma unroll
    for (int i = 0; i < 8; i++) {
        int r = ty + i * 8;
        t[tx][r] = src[zs + (size_t)(r0 + r) * C + c0 + tx];
    }
    __syncthreads();
    __half2* d2 = (__half2*)(dst + zs);
#pragma unroll
    for (int j = 0; j < 4; j++) {
        int c = ty + j * 8;
        d2[((size_t)(c0 + c) * R + r0) / 2 + tx] = __floats2half2_rn(t[c][2 * tx], t[c][2 * tx + 1]);
    }
}

// ============================================================================
// Mainloop pieces
// ============================================================================
struct Frag {
    float acc[2][8][4];
};

__device__ __forceinline__ void load_frags(uint32_t sA, uint32_t sB, int kk,
                                           uint32_t (&a)[2][4], uint32_t (&b)[8][2],
                                           int wm, int wn, int lane) {
    const int l7 = lane & 7, l15 = lane & 15;
    const int lb8 = (lane >> 3) & 1, lb16 = (lane >> 4) & 1;
#pragma unroll
    for (int i = 0; i < 2; i++) {
        uint32_t t[4];
        ldsm4(t, swaddr(sA, wm + i * 16 + l15, (kk << 5) | (lb16 << 4)));
        a[i][0] = t[0]; a[i][1] = t[1]; a[i][2] = t[2]; a[i][3] = t[3];
    }
#pragma unroll
    for (int jj = 0; jj < 4; jj++) {
        uint32_t t[4];
        ldsm4(t, swaddr(sB, wn + jj * 16 + l7 + (lb16 << 3), (kk << 5) | (lb8 << 4)));
        b[2 * jj][0] = t[0];     b[2 * jj][1] = t[1];
        b[2 * jj + 1][0] = t[2]; b[2 * jj + 1][1] = t[3];
    }
}

__device__ __forceinline__ void mma_all(Frag& F, const uint32_t (&a)[2][4],
                                        const uint32_t (&b)[8][2]) {
#pragma unroll
    for (int i = 0; i < 2; i++)
#pragma unroll
        for (int j = 0; j < 8; j++)
            mma16816(F.acc[i][j], a[i], b[j]);
}

// ============================================================================
// GEMM1: hid[e,t,d] = rw[t,e] * glu(X @ W1[e] + b1[e])
// ============================================================================
__global__ __launch_bounds__(256, 2)
void gemm1_hk(const float* __restrict__ b1, const float* __restrict__ rw) {
    extern __shared__ __align__(1024) char smem[];
    const uint32_t sb = smem_u32(smem);
    const int tid = threadIdx.x, lane = tid & 31, warp = tid >> 5;
    const int wm = (warp & 3) * 32, wn = (warp >> 2) * 64;
    const int m0 = blockIdx.x * BM, n0 = blockIdx.y * BN, e = blockIdx.z;

    Frag F;
#pragma unroll
    for (int i = 0; i < 2; i++)
#pragma unroll
        for (int j = 0; j < 8; j++)
#pragma unroll
            for (int q = 0; q < 4; q++) F.acc[i][j][q] = 0.f;

    const __half* Ab = g_xh + (size_t)m0 * H_;
    const __half* Bb = g_w1t + ((size_t)e * TWOD_ + n0) * H_;
    const int NKT = H_ / BK;  // 45 (divisible by NS=3)

    auto copy_slab = [&](int kt, int buf) {
        uint32_t sA = sb + buf * STAGE_BYTES, sB = sA + A_BYTES;
        const __half* ga = Ab + kt * BK;
        const __half* gb = Bb + kt * BK;
#pragma unroll
        for (int it = 0; it < 4; it++) {
            int ch = tid + it * 256;
            int r = ch >> 3, kc = ch & 7;
            cpa16(swaddr(sA, r, kc * 16), ga + (size_t)r * H_ + kc * 8, 16);
        }
#pragma unroll
        for (int it = 0; it < 4; it++) {
            int ch = tid + it * 256;
            int r = ch >> 3, kc = ch & 7;
            cpa16(swaddr(sB, r, kc * 16), gb + (size_t)r * H_ + kc * 8, 16);
        }
    };

    // branch-free slab body: frag(kk0) first, copy-issue under its latency
    auto slab_body = [&](int kt, int buf) {
        CP_WAIT(1);
        __syncthreads();
        uint32_t sA = sb + buf * STAGE_BYTES, sB = sA + A_BYTES;
        uint32_t a[2][4], b[8][2];
        load_frags(sA, sB, 0, a, b, wm, wn, lane);
        int nk = kt + 2 < NKT ? kt + 2 : NKT - 1;   // clamped: dead-stage rewrite at tail
        int nb = buf + 2 >= NS ? buf + 2 - NS : buf + 2;
        copy_slab(nk, nb);
        CP_COMMIT();
        mma_all(F, a, b);
#pragma unroll
        for (int kk = 1; kk < BK / 16; kk++) {
            load_frags(sA, sB, kk, a, b, wm, wn, lane);
            mma_all(F, a, b);
        }
    };

    copy_slab(0, 0); CP_COMMIT();
    copy_slab(1, 1); CP_COMMIT();
    for (int kt = 0; kt < NKT; kt += 3) {
        slab_body(kt, 0);
        slab_body(kt + 1, 1);
        slab_body(kt + 2, 2);
    }
    CP_WAIT(0);
    __syncthreads();

    // bias tile -> smem
    float* bsm = (float*)smem;
    for (int i = tid; i < BN; i += 256) bsm[i] = b1[(size_t)e * TWOD_ + n0 + i];
    __syncthreads();

    const int tig = lane & 3, gid = lane >> 2;
#pragma unroll
    for (int i = 0; i < 2; i++) {
#pragma unroll
        for (int s = 0; s < 2; s++) {
            int row = m0 + wm + i * 16 + s * 8 + gid;
            float rwv = rw[(size_t)row * E_ + e];
            __half* hd = g_hid + ((size_t)e * T_ + row) * D_ + (n0 >> 1);
#pragma unroll
            for (int j = 0; j < 8; j++) {
                int cl = wn + j * 8 + 2 * tig;
                float g = F.acc[i][j][2 * s]     + bsm[cl];
                float u = F.acc[i][j][2 * s + 1] + bsm[cl + 1];
                g = fminf(g, 7.0f);
                u = fminf(fmaxf(u, -7.0f), 7.0f);
                float sig = 1.0f / (1.0f + __expf(-1.702f * g));
                hd[cl >> 1] = __float2half_rn(rwv * (u + 1.0f) * (g * sig));
            }
        }
    }
}

// ============================================================================
// GEMM2 (split-K over experts): g_part[z][t,h] = sum_{e in split z} hid@W2t
// ============================================================================
__global__ __launch_bounds__(256, 2)
void gemm2_hk() {
    extern __shared__ __align__(1024) char smem[];
    const uint32_t sb = smem_u32(smem);
    const int tid = threadIdx.x, lane = tid & 31, warp = tid >> 5;
    const int wm = (warp & 3) * 32, wn = (warp >> 2) * 64;
    const int m0 = blockIdx.x * BM, n0 = blockIdx.y * BN, z = blockIdx.z;

    Frag F;
#pragma unroll
    for (int i = 0; i < 2; i++)
#pragma unroll
        for (int j = 0; j < 8; j++)
#pragma unroll
            for (int q = 0; q < 4; q++) F.acc[i][j][q] = 0.f;

    const int KPE = D_ / BK;        // 45
    const int NKT = EPS * KPE;      // 90 (divisible by NS=3)

    auto copy_slab = [&](int kt, int buf) {
        int e = z * EPS + kt / KPE, kin = kt % KPE;
        uint32_t sA = sb + buf * STAGE_BYTES, sB = sA + A_BYTES;
        const __half* ga = g_hid + ((size_t)e * T_ + m0) * D_ + kin * BK;
        const __half* gb = g_w2t + ((size_t)e * H_ + n0) * D_ + kin * BK;
#pragma unroll
        for (int it = 0; it < 4; it++) {
            int ch = tid + it * 256;
            int r = ch >> 3, kc = ch & 7;
            cpa16(swaddr(sA, r, kc * 16), ga + (size_t)r * D_ + kc * 8, 16);
        }
#pragma unroll
        for (int it = 0; it < 4; it++) {
            int ch = tid + it * 256;
            int r = ch >> 3, kc = ch & 7;
            int ok = (n0 + r < H_) ? 16 : 0;     // tail rows zero-filled
            cpa16(swaddr(sB, r, kc * 16), gb + (size_t)r * D_ + kc * 8, ok);
        }
    };

    auto slab_body = [&](int kt, int buf) {
        CP_WAIT(1);
        __syncthreads();
        uint32_t sA = sb + buf * STAGE_BYTES, sB = sA + A_BYTES;
        uint32_t a[2][4], b[8][2];
        load_frags(sA, sB, 0, a, b, wm, wn, lane);
        int nk = kt + 2 < NKT ? kt + 2 : NKT - 1;
        int nb = buf + 2 >= NS ? buf + 2 - NS : buf + 2;
        copy_slab(nk, nb);
        CP_COMMIT();
        mma_all(F, a, b);
#pragma unroll
        for (int kk = 1; kk < BK / 16; kk++) {
            load_frags(sA, sB, kk, a, b, wm, wn, lane);
            mma_all(F, a, b);
        }
    };

    copy_slab(0, 0); CP_COMMIT();
    copy_slab(1, 1); CP_COMMIT();
    for (int kt = 0; kt < NKT; kt += 3) {
        slab_body(kt, 0);
        slab_body(kt + 1, 1);
        slab_body(kt + 2, 2);
    }

    const int tig = lane & 3, gid = lane >> 2;
    float* pd = g_part + (size_t)z * T_ * H_;
#pragma unroll
    for (int j = 0; j < 8; j++) {
        int cl = wn + j * 8 + 2 * tig;
        int gc = n0 + cl;
        if (gc < H_) {
#pragma unroll
            for (int i = 0; i < 2; i++)
#pragma unroll
                for (int s = 0; s < 2; s++) {
                    int row = m0 + wm + i * 16 + s * 8 + gid;
                    float2 v = make_float2(F.acc[i][j][2 * s], F.acc[i][j][2 * s + 1]);
                    *(float2*)(pd + (size_t)row * H_ + gc) = v;
                }
        }
    }
}

// ============================================================================
// Reduce: out = sum_z g_part[z] + sum_e rw[t,e]*b2[e,h]
// ============================================================================
__global__ __launch_bounds__(256)
void k_reduce(const float* __restrict__ rw, const float* __restrict__ b2,
              float* __restrict__ out) {
    size_t i4 = (size_t)blockIdx.x * blockDim.x + threadIdx.x;   // float4 index
    const size_t N4 = (size_t)T_ * H_ / 4;
    if (i4 >= N4) return;
    size_t idx = i4 * 4;
    int t = (int)(idx / H_), h = (int)(idx % H_);   // H_%4==0 -> same row

    const float4* p0 = (const float4*)g_part;
    float4 a0 = p0[i4];
    float4 a1 = p0[N4 + i4];
    float4 a2 = p0[2 * N4 + i4];
    float4 a3 = p0[3 * N4 + i4];
    float4 acc = make_float4(a0.x + a1.x + a2.x + a3.x,
                             a0.y + a1.y + a2.y + a3.y,
                             a0.z + a1.z + a2.z + a3.z,
                             a0.w + a1.w + a2.w + a3.w);

    const float4* rp = (const float4*)(rw + (size_t)t * E_);
    float4 r0 = rp[0], r1 = rp[1];
    float rr[E_] = {r0.x, r0.y, r0.z, r0.w, r1.x, r1.y, r1.z, r1.w};
#pragma unroll
    for (int e = 0; e < E_; e++) {
        float4 bb = *(const float4*)(b2 + (size_t)e * H_ + h);
        acc.x += rr[e] * bb.x;
        acc.y += rr[e] * bb.y;
        acc.z += rr[e] * bb.z;
        acc.w += rr[e] * bb.w;
    }
    ((float4*)out)[i4] = acc;
}

// ---------------- host ----------------
extern "C" void kernel_launch(void* const* d_in, const int* in_sizes, int n_in,
                              void* d_out, int out_size) {
    (void)in_sizes; (void)n_in; (void)out_size;
    const float* x  = (const float*)d_in[0];
    const float* rw = (const float*)d_in[1];
    const float* w1 = (const float*)d_in[2];
    const float* b1 = (const float*)d_in[3];
    const float* w2 = (const float*)d_in[4];
    const float* b2 = (const float*)d_in[5];
    float* out = (float*)d_out;

    void *p_w1t, *p_w2t;
    cudaGetSymbolAddress(&p_w1t, g_w1t);
    cudaGetSymbolAddress(&p_w2t, g_w2t);

    cudaFuncSetAttribute(gemm1_hk, cudaFuncAttributeMaxDynamicSharedMemorySize, SMEM_BYTES);
    cudaFuncSetAttribute(gemm2_hk, cudaFuncAttributeMaxDynamicSharedMemorySize, SMEM_BYTES);

    k_cvt_half<<<2048, 256>>>(x);
    k_transpose_h<<<dim3(TWOD_ / 32, H_ / 64, E_), dim3(32, 8)>>>(w1, (__half*)p_w1t, H_, TWOD_);
    k_transpose_h<<<dim3(H_ / 32, D_ / 64, E_), dim3(32, 8)>>>(w2, (__half*)p_w2t, D_, H_);

    gemm1_hk<<<dim3(T_ / BM, TWOD_ / BN, E_), 256, SMEM_BYTES>>>(b1, rw);
    gemm2_hk<<<dim3(T_ / BM, (H_ + BN - 1) / BN, SPLITK), 256, SMEM_BYTES>>>();
    k_reduce<<<(T_ * H_ / 4 + 255) / 256, 256>>>(rw, b2, out);
}